// round 8
// baseline (speedup 1.0000x reference)
#include <cuda_runtime.h>
#include <cstdint>

// Problem constants (fixed by the dataset)
#define BB     2048
#define NN     512
#define XX     32
#define HH     64

#define THREADS 512
#define BC      16       // batches per CTA
#define VSTR    20       // padded row stride (floats); 80B = 16B-aligned, bank-skewed
#define KTOT    96       // 64 h-rows + 32 x-rows
#define JN      24       // k's per thread (KTOT / 4 kh-groups)

typedef unsigned long long u64;

static __device__ __forceinline__ u64 pack2(float lo, float hi) {
    u64 r;
    asm("mov.b64 %0, {%1, %2};" : "=l"(r) : "f"(lo), "f"(hi));
    return r;
}
static __device__ __forceinline__ u64 ffma2(u64 a, u64 b, u64 c) {
    u64 d;
    asm("fma.rn.f32x2 %0, %1, %2, %3;" : "=l"(d) : "l"(a), "l"(b), "l"(c));
    return d;
}
static __device__ __forceinline__ u64 add2(u64 a, u64 b) {
    u64 d;
    asm("add.rn.f32x2 %0, %1, %2;" : "=l"(d) : "l"(a), "l"(b));
    return d;
}

static __device__ __forceinline__ float sigm_fast(float z) {
    return __fdividef(1.0f, 1.0f + __expf(-z));
}
// tanh(z) = 2/(1+exp(-2z)) - 1 : safe for exp overflow in either direction
static __device__ __forceinline__ float tanh_fast(float z) {
    float t = __expf(-2.0f * z);
    return 2.0f * __fdividef(1.0f, 1.0f + t) - 1.0f;
}

__global__ void __launch_bounds__(THREADS, 1)
lstm_scan_kernel(const float* __restrict__ x,
                 const float* __restrict__ ig_w_c, const float* __restrict__ ig_w_h,
                 const float* __restrict__ ig_w_x, const float* __restrict__ ig_b,
                 const float* __restrict__ fg_w_c, const float* __restrict__ fg_w_h,
                 const float* __restrict__ fg_w_x, const float* __restrict__ fg_b,
                 const float* __restrict__ in_w_h, const float* __restrict__ in_w_x,
                 const float* __restrict__ in_b,
                 const float* __restrict__ og_w_cn, const float* __restrict__ og_w_h,
                 const float* __restrict__ og_w_x, const float* __restrict__ og_b,
                 float* __restrict__ out)
{
    // static shared: two state buffers [KTOT][VSTR] + z scratch [4][64][VSTR]
    __shared__ __align__(16) float vbuf[2][KTOT * VSTR];
    __shared__ __align__(16) float zbuf[4 * HH * VSTR];

    const int tid = threadIdx.x;
    const int u   = tid >> 3;          // hidden unit 0..63 (shared by both roles)
    const int gp  = (tid >> 2) & 1;    // gate pair: 0 -> (ig,fg), 1 -> (in,og)
    const int kh  = tid & 3;           // k-quarter, lives in lane bits 0..1
    const int bs  = tid & 7;           // epilogue batch-slot (2 batches: 2bs, 2bs+1)
    const int b0  = blockIdx.x * BC;

    const int g0 = 2 * gp, g1 = 2 * gp + 1;

    // ---------------- prologue: weights -> registers ------------------------
    const float* WH[4] = {ig_w_h, fg_w_h, in_w_h, og_w_h};
    const float* WX[4] = {ig_w_x, fg_w_x, in_w_x, og_w_x};
    const float* BV[4] = {ig_b,   fg_b,   in_b,   og_b};

    float2 w2[JN];                     // (w_g0[k], w_g1[k]) for k = 4j + kh
    #pragma unroll
    for (int j = 0; j < JN; j++) {
        int k = 4 * j + kh;
        float a, b;
        if (k < 64) { a = WH[g0][u * 64 + k];        b = WH[g1][u * 64 + k]; }
        else        { a = WX[g0][u * 32 + (k - 64)]; b = WX[g1][u * 32 + (k - 64)]; }
        w2[j] = make_float2(a, b);
    }
    const float bg0  = BV[g0][u];
    const float bg1  = BV[g1][u];
    const float wci  = ig_w_c[u];
    const float wcf  = fg_w_c[u];
    const float wocn = og_w_cn[u];

    // ---------------- stage initial state -----------------------------------
    for (int i = tid; i < 64 * VSTR; i += THREADS) vbuf[0][i] = 0.0f;  // h_0 = 0
    const int xb = tid >> 5;          // batch 0..15 for x staging
    const int xk = tid & 31;          // x feature 0..31
    const float* xrow = x + (size_t)(b0 + xb) * (NN * XX) + xk;
    vbuf[0][(64 + xk) * VSTR + xb] = xrow[0];
    __syncthreads();

    float c0 = 0.0f, c1 = 0.0f;       // cell state for batches 2bs, 2bs+1
    float h0 = 0.0f, h1 = 0.0f;

    for (int t = 0; t < NN; t++) {
        const float* vc = vbuf[t & 1];
        float*       vn = vbuf[(t + 1) & 1];

        // prefetch x_{t+1} (latency hidden under the FFMA phase)
        float xpre = 0.0f;
        if (t + 1 < NN) xpre = xrow[(t + 1) * XX];

        // ---- FFMA phase: partial dot over k = 4j + kh, all 16 batches ------
        u64 a0[8], a1[8];              // (z[2p], z[2p+1]) per gate
        {
            u64 i0 = (kh == 0) ? pack2(bg0, bg0) : 0ull;
            u64 i1 = (kh == 0) ? pack2(bg1, bg1) : 0ull;
            #pragma unroll
            for (int p = 0; p < 8; p++) { a0[p] = i0; a1[p] = i1; }
        }
        #pragma unroll
        for (int j = 0; j < JN; j++) {
            const ulonglong2* row =
                reinterpret_cast<const ulonglong2*>(&vc[(4 * j + kh) * VSTR]);
            ulonglong2 q0 = row[0], q1 = row[1], q2 = row[2], q3 = row[3];
            u64 wA = pack2(w2[j].x, w2[j].x);
            u64 wB = pack2(w2[j].y, w2[j].y);
            a0[0] = ffma2(wA, q0.x, a0[0]);  a1[0] = ffma2(wB, q0.x, a1[0]);
            a0[1] = ffma2(wA, q0.y, a0[1]);  a1[1] = ffma2(wB, q0.y, a1[1]);
            a0[2] = ffma2(wA, q1.x, a0[2]);  a1[2] = ffma2(wB, q1.x, a1[2]);
            a0[3] = ffma2(wA, q1.y, a0[3]);  a1[3] = ffma2(wB, q1.y, a1[3]);
            a0[4] = ffma2(wA, q2.x, a0[4]);  a1[4] = ffma2(wB, q2.x, a1[4]);
            a0[5] = ffma2(wA, q2.y, a0[5]);  a1[5] = ffma2(wB, q2.y, a1[5]);
            a0[6] = ffma2(wA, q3.x, a0[6]);  a1[6] = ffma2(wB, q3.x, a1[6]);
            a0[7] = ffma2(wA, q3.y, a0[7]);  a1[7] = ffma2(wB, q3.y, a1[7]);
        }

        // ---- reduce over kh (lane bits 0,1) via bfly shuffles --------------
        #pragma unroll
        for (int p = 0; p < 8; p++) {
            a0[p] = add2(a0[p], __shfl_xor_sync(0xffffffffu, a0[p], 1));
            a1[p] = add2(a1[p], __shfl_xor_sync(0xffffffffu, a1[p], 1));
        }
        #pragma unroll
        for (int p = 0; p < 8; p++) {
            a0[p] = add2(a0[p], __shfl_xor_sync(0xffffffffu, a0[p], 2));
            a1[p] = add2(a1[p], __shfl_xor_sync(0xffffffffu, a1[p], 2));
        }

        // ---- scatter z to shared: each kh lane stores one quarter ----------
        // constant reg-array indices per branch (no local spills)
        if (kh == 0) {
            ulonglong2* d = reinterpret_cast<ulonglong2*>(&zbuf[(g0 * HH + u) * VSTR + 0]);
            d[0] = make_ulonglong2(a0[0], a0[1]);
            d[1] = make_ulonglong2(a0[2], a0[3]);
        } else if (kh == 1) {
            ulonglong2* d = reinterpret_cast<ulonglong2*>(&zbuf[(g0 * HH + u) * VSTR + 8]);
            d[0] = make_ulonglong2(a0[4], a0[5]);
            d[1] = make_ulonglong2(a0[6], a0[7]);
        } else if (kh == 2) {
            ulonglong2* d = reinterpret_cast<ulonglong2*>(&zbuf[(g1 * HH + u) * VSTR + 0]);
            d[0] = make_ulonglong2(a1[0], a1[1]);
            d[1] = make_ulonglong2(a1[2], a1[3]);
        } else {
            ulonglong2* d = reinterpret_cast<ulonglong2*>(&zbuf[(g1 * HH + u) * VSTR + 8]);
            d[0] = make_ulonglong2(a1[4], a1[5]);
            d[1] = make_ulonglong2(a1[6], a1[7]);
        }
        __syncthreads();

        // ---- epilogue: thread (u, bs) handles batches 2bs, 2bs+1 -----------
        float2 zi = *reinterpret_cast<const float2*>(&zbuf[(0 * HH + u) * VSTR + 2 * bs]);
        float2 zf = *reinterpret_cast<const float2*>(&zbuf[(1 * HH + u) * VSTR + 2 * bs]);
        float2 zn = *reinterpret_cast<const float2*>(&zbuf[(2 * HH + u) * VSTR + 2 * bs]);
        float2 zo = *reinterpret_cast<const float2*>(&zbuf[(3 * HH + u) * VSTR + 2 * bs]);

        {
            float ig  = sigm_fast(zi.x + wci * c0);
            float fg  = sigm_fast(zf.x + wcf * c0);
            float inn = tanh_fast(zn.x);
            float cn  = fg * c0 + ig * inn;
            float og  = sigm_fast(zo.x + wocn * cn);
            h0 = og * tanh_fast(cn);
            c0 = cn;
        }
        {
            float ig  = sigm_fast(zi.y + wci * c1);
            float fg  = sigm_fast(zf.y + wcf * c1);
            float inn = tanh_fast(zn.y);
            float cn  = fg * c1 + ig * inn;
            float og  = sigm_fast(zo.y + wocn * cn);
            h1 = og * tanh_fast(cn);
            c1 = cn;
        }

        // publish h_{t+1} and x_{t+1} into the other buffer
        *reinterpret_cast<float2*>(&vn[u * VSTR + 2 * bs]) = make_float2(h0, h1);
        if (t + 1 < NN) vn[(64 + xk) * VSTR + xb] = xpre;
        __syncthreads();
    }

    // final h -> out[B, H]
    out[(size_t)(b0 + 2 * bs) * HH + u]     = h0;
    out[(size_t)(b0 + 2 * bs + 1) * HH + u] = h1;
}

extern "C" void kernel_launch(void* const* d_in, const int* in_sizes, int n_in,
                              void* d_out, int out_size)
{
    (void)in_sizes; (void)n_in; (void)out_size;
    const float* x       = (const float*)d_in[0];
    const float* ig_w_c  = (const float*)d_in[1];
    const float* ig_w_h  = (const float*)d_in[2];
    const float* ig_w_x  = (const float*)d_in[3];
    const float* ig_b    = (const float*)d_in[4];
    const float* fg_w_c  = (const float*)d_in[5];
    const float* fg_w_h  = (const float*)d_in[6];
    const float* fg_w_x  = (const float*)d_in[7];
    const float* fg_b    = (const float*)d_in[8];
    const float* in_w_h  = (const float*)d_in[9];
    const float* in_w_x  = (const float*)d_in[10];
    const float* in_b    = (const float*)d_in[11];
    const float* og_w_cn = (const float*)d_in[12];
    const float* og_w_h  = (const float*)d_in[13];
    const float* og_w_x  = (const float*)d_in[14];
    const float* og_b    = (const float*)d_in[15];
    float* out = (float*)d_out;

    dim3 grid(BB / BC);   // 128 CTAs
    dim3 block(THREADS);
    lstm_scan_kernel<<<grid, block>>>(
        x, ig_w_c, ig_w_h, ig_w_x, ig_b,
        fg_w_c, fg_w_h, fg_w_x, fg_b,
        in_w_h, in_w_x, in_b,
        og_w_cn, og_w_h, og_w_x, og_b,
        out);
}

// round 13
// speedup vs baseline: 1.4514x; 1.4514x over previous
#include <cuda_runtime.h>
#include <cstdint>

// Problem constants (fixed by the dataset)
#define BB     2048
#define NN     512
#define XX     32
#define HH     64

#define THREADS 256
#define BC      16       // batches per CTA
#define VSTR    20       // padded row stride (floats); 80B, 16B-aligned, bank-skewed
#define KTOT    96       // 64 h-rows + 32 x-rows
#define JN      48       // k's per thread (KTOT / 2 kh-groups)

typedef unsigned long long u64;

static __device__ __forceinline__ u64 pack2(float lo, float hi) {
    u64 r;
    asm("mov.b64 %0, {%1, %2};" : "=l"(r) : "f"(lo), "f"(hi));
    return r;
}
static __device__ __forceinline__ u64 ffma2(u64 a, u64 b, u64 c) {
    u64 d;
    asm("fma.rn.f32x2 %0, %1, %2, %3;" : "=l"(d) : "l"(a), "l"(b), "l"(c));
    return d;
}
static __device__ __forceinline__ u64 add2(u64 a, u64 b) {
    u64 d;
    asm("add.rn.f32x2 %0, %1, %2;" : "=l"(d) : "l"(a), "l"(b));
    return d;
}

static __device__ __forceinline__ float sigm_fast(float z) {
    return __fdividef(1.0f, 1.0f + __expf(-z));
}
// tanh(z) = 2/(1+exp(-2z)) - 1 : safe for exp overflow in either direction
static __device__ __forceinline__ float tanh_fast(float z) {
    float t = __expf(-2.0f * z);
    return 2.0f * __fdividef(1.0f, 1.0f + t) - 1.0f;
}

__global__ void __launch_bounds__(THREADS, 1)
lstm_scan_kernel(const float* __restrict__ x,
                 const float* __restrict__ ig_w_c, const float* __restrict__ ig_w_h,
                 const float* __restrict__ ig_w_x, const float* __restrict__ ig_b,
                 const float* __restrict__ fg_w_c, const float* __restrict__ fg_w_h,
                 const float* __restrict__ fg_w_x, const float* __restrict__ fg_b,
                 const float* __restrict__ in_w_h, const float* __restrict__ in_w_x,
                 const float* __restrict__ in_b,
                 const float* __restrict__ og_w_cn, const float* __restrict__ og_w_h,
                 const float* __restrict__ og_w_x, const float* __restrict__ og_b,
                 float* __restrict__ out)
{
    // static shared: two state buffers [KTOT][VSTR] + z scratch [4][64][VSTR]
    __shared__ __align__(16) float vbuf[2][KTOT * VSTR];
    __shared__ __align__(16) float zbuf[4 * HH * VSTR];

    const int tid = threadIdx.x;
    const int u   = tid >> 2;          // hidden unit 0..63 (FFMA-phase role)
    const int gp  = (tid >> 1) & 1;    // gate pair: 0 -> (ig,fg), 1 -> (in,og)
    const int kh  = tid & 1;           // k-half, lives in lane bit 0
    const int ue  = tid >> 2;          // epilogue hidden unit (same split)
    const int es  = tid & 3;           // epilogue batch-slot (4 batches: 4es..4es+3)
    const int b0  = blockIdx.x * BC;

    const int g0 = 2 * gp, g1 = 2 * gp + 1;

    // ---------------- prologue: weights -> registers ------------------------
    const float* WH[4] = {ig_w_h, fg_w_h, in_w_h, og_w_h};
    const float* WX[4] = {ig_w_x, fg_w_x, in_w_x, og_w_x};
    const float* BV[4] = {ig_b,   fg_b,   in_b,   og_b};

    float2 w2[JN];                     // (w_g0[k], w_g1[k]) for k = 2j + kh
    #pragma unroll
    for (int j = 0; j < JN; j++) {
        int k = 2 * j + kh;
        float a, b;
        if (k < 64) { a = WH[g0][u * 64 + k];        b = WH[g1][u * 64 + k]; }
        else        { a = WX[g0][u * 32 + (k - 64)]; b = WX[g1][u * 32 + (k - 64)]; }
        w2[j] = make_float2(a, b);
    }
    const float bg0  = BV[g0][u];
    const float bg1  = BV[g1][u];
    const float wci  = ig_w_c[ue];
    const float wcf  = fg_w_c[ue];
    const float wocn = og_w_cn[ue];

    // ---------------- stage initial state -----------------------------------
    for (int i = tid; i < 64 * VSTR; i += THREADS) vbuf[0][i] = 0.0f;  // h_0 = 0
    const int xb = tid >> 4;          // batch 0..15 for x staging
    const int xk = (tid * 2) & 31;    // x feature (even) 0..30
    const float* xrow = x + (size_t)(b0 + xb) * (NN * XX) + xk;
    {
        float2 xp = *reinterpret_cast<const float2*>(xrow);
        vbuf[0][(64 + xk) * VSTR + xb]     = xp.x;
        vbuf[0][(64 + xk + 1) * VSTR + xb] = xp.y;
    }
    __syncthreads();

    float c[4] = {0.0f, 0.0f, 0.0f, 0.0f};   // cell state, batches 4es..4es+3
    float h[4] = {0.0f, 0.0f, 0.0f, 0.0f};

    for (int t = 0; t < NN; t++) {
        const float* vc = vbuf[t & 1];
        float*       vn = vbuf[(t + 1) & 1];

        // prefetch x_{t+1} (latency hidden under the FFMA phase)
        float2 xp = make_float2(0.0f, 0.0f);
        if (t + 1 < NN)
            xp = *reinterpret_cast<const float2*>(&xrow[(t + 1) * XX]);

        // ---- FFMA phase: partial dot over k = 2j + kh, all 16 batches ------
        u64 a0[8], a1[8];              // gate g0 / g1 accumulators (16 batches)
        {
            u64 i0 = (kh == 0) ? pack2(bg0, bg0) : 0ull;
            u64 i1 = (kh == 0) ? pack2(bg1, bg1) : 0ull;
            #pragma unroll
            for (int p = 0; p < 8; p++) { a0[p] = i0; a1[p] = i1; }
        }
        #pragma unroll
        for (int j = 0; j < JN; j++) {
            const ulonglong2* row =
                reinterpret_cast<const ulonglong2*>(&vc[(2 * j + kh) * VSTR]);
            ulonglong2 q0 = row[0], q1 = row[1], q2 = row[2], q3 = row[3];
            u64 wA = pack2(w2[j].x, w2[j].x);
            u64 wB = pack2(w2[j].y, w2[j].y);
            a0[0] = ffma2(wA, q0.x, a0[0]);  a1[0] = ffma2(wB, q0.x, a1[0]);
            a0[1] = ffma2(wA, q0.y, a0[1]);  a1[1] = ffma2(wB, q0.y, a1[1]);
            a0[2] = ffma2(wA, q1.x, a0[2]);  a1[2] = ffma2(wB, q1.x, a1[2]);
            a0[3] = ffma2(wA, q1.y, a0[3]);  a1[3] = ffma2(wB, q1.y, a1[3]);
            a0[4] = ffma2(wA, q2.x, a0[4]);  a1[4] = ffma2(wB, q2.x, a1[4]);
            a0[5] = ffma2(wA, q2.y, a0[5]);  a1[5] = ffma2(wB, q2.y, a1[5]);
            a0[6] = ffma2(wA, q3.x, a0[6]);  a1[6] = ffma2(wB, q3.x, a1[6]);
            a0[7] = ffma2(wA, q3.y, a0[7]);  a1[7] = ffma2(wB, q3.y, a1[7]);
        }

        // ---- reduce over kh (lane bit 0): one bfly round -------------------
        #pragma unroll
        for (int p = 0; p < 8; p++) {
            a0[p] = add2(a0[p], __shfl_xor_sync(0xffffffffu, a0[p], 1));
            a1[p] = add2(a1[p], __shfl_xor_sync(0xffffffffu, a1[p], 1));
        }

        // ---- scatter z to shared: kh=0 stores batches 0-7, kh=1 -> 8-15 ----
        if (kh == 0) {
            ulonglong2* d0 = reinterpret_cast<ulonglong2*>(&zbuf[(g0 * HH + u) * VSTR + 0]);
            d0[0] = make_ulonglong2(a0[0], a0[1]);
            d0[1] = make_ulonglong2(a0[2], a0[3]);
            ulonglong2* d1 = reinterpret_cast<ulonglong2*>(&zbuf[(g1 * HH + u) * VSTR + 0]);
            d1[0] = make_ulonglong2(a1[0], a1[1]);
            d1[1] = make_ulonglong2(a1[2], a1[3]);
        } else {
            ulonglong2* d0 = reinterpret_cast<ulonglong2*>(&zbuf[(g0 * HH + u) * VSTR + 8]);
            d0[0] = make_ulonglong2(a0[4], a0[5]);
            d0[1] = make_ulonglong2(a0[6], a0[7]);
            ulonglong2* d1 = reinterpret_cast<ulonglong2*>(&zbuf[(g1 * HH + u) * VSTR + 8]);
            d1[0] = make_ulonglong2(a1[4], a1[5]);
            d1[1] = make_ulonglong2(a1[6], a1[7]);
        }
        __syncthreads();

        // ---- epilogue: thread (ue, es) handles batches 4es..4es+3 ----------
        float4 zi = *reinterpret_cast<const float4*>(&zbuf[(0 * HH + ue) * VSTR + 4 * es]);
        float4 zf = *reinterpret_cast<const float4*>(&zbuf[(1 * HH + ue) * VSTR + 4 * es]);
        float4 zn = *reinterpret_cast<const float4*>(&zbuf[(2 * HH + ue) * VSTR + 4 * es]);
        float4 zo = *reinterpret_cast<const float4*>(&zbuf[(3 * HH + ue) * VSTR + 4 * es]);

        const float ziv[4] = {zi.x, zi.y, zi.z, zi.w};
        const float zfv[4] = {zf.x, zf.y, zf.z, zf.w};
        const float znv[4] = {zn.x, zn.y, zn.z, zn.w};
        const float zov[4] = {zo.x, zo.y, zo.z, zo.w};

        #pragma unroll
        for (int r = 0; r < 4; r++) {
            float ig  = sigm_fast(ziv[r] + wci * c[r]);
            float fg  = sigm_fast(zfv[r] + wcf * c[r]);
            float inn = tanh_fast(znv[r]);
            float cn  = fg * c[r] + ig * inn;
            float og  = sigm_fast(zov[r] + wocn * cn);
            h[r] = og * tanh_fast(cn);
            c[r] = cn;
        }

        // publish h_{t+1} and x_{t+1} into the other buffer
        *reinterpret_cast<float4*>(&vn[ue * VSTR + 4 * es]) =
            make_float4(h[0], h[1], h[2], h[3]);
        if (t + 1 < NN) {
            vn[(64 + xk) * VSTR + xb]     = xp.x;
            vn[(64 + xk + 1) * VSTR + xb] = xp.y;
        }
        __syncthreads();
    }

    // final h -> out[B, H]
    #pragma unroll
    for (int r = 0; r < 4; r++) {
        out[(size_t)(b0 + 4 * es + r) * HH + ue] = h[r];
    }
}

extern "C" void kernel_launch(void* const* d_in, const int* in_sizes, int n_in,
                              void* d_out, int out_size)
{
    (void)in_sizes; (void)n_in; (void)out_size;
    const float* x       = (const float*)d_in[0];
    const float* ig_w_c  = (const float*)d_in[1];
    const float* ig_w_h  = (const float*)d_in[2];
    const float* ig_w_x  = (const float*)d_in[3];
    const float* ig_b    = (const float*)d_in[4];
    const float* fg_w_c  = (const float*)d_in[5];
    const float* fg_w_h  = (const float*)d_in[6];
    const float* fg_w_x  = (const float*)d_in[7];
    const float* fg_b    = (const float*)d_in[8];
    const float* in_w_h  = (const float*)d_in[9];
    const float* in_w_x  = (const float*)d_in[10];
    const float* in_b    = (const float*)d_in[11];
    const float* og_w_cn = (const float*)d_in[12];
    const float* og_w_h  = (const float*)d_in[13];
    const float* og_w_x  = (const float*)d_in[14];
    const float* og_b    = (const float*)d_in[15];
    float* out = (float*)d_out;

    dim3 grid(BB / BC);   // 128 CTAs
    dim3 block(THREADS);
    lstm_scan_kernel<<<grid, block>>>(
        x, ig_w_c, ig_w_h, ig_w_x, ig_b,
        fg_w_c, fg_w_h, fg_w_x, fg_b,
        in_w_h, in_w_x, in_b,
        og_w_cn, og_w_h, og_w_x, og_b,
        out);
}